// round 1
// baseline (speedup 1.0000x reference)
#include <cuda_runtime.h>

// ---------------- problem constants ----------------
namespace cfg {
constexpr int B_ = 2, T_ = 8, H_ = 128, W_ = 192, C_ = 96;
constexpr int NH = 2, KD = 8, HK = 16;          // heads, key dim, NH*KD
constexpr int NTOK = 64;                        // tokens per spatial window (8x8)
constexpr int NWH = 16, NWW = 24;               // windows along H, W
constexpr int NTOTAL = B_ * T_ * H_ * W_;       // 393216 tokens
}
using namespace cfg;

__device__ float g_buf1[B_*T_*H_*W_*C_];
__device__ float g_buf2[B_*T_*H_*W_*C_];

#define SCALEF 0.35355339059327373f
#define EPSF   1e-3f

// =====================================================================
// Kernel 1: LN1 + shifted-window spatial MSA
// grid = (B*T) * (NWH*NWW) = 6144 blocks, 128 threads
// =====================================================================
__global__ __launch_bounds__(128) void k_spatial(
    const float* __restrict__ x,
    const float* __restrict__ g1, const float* __restrict__ b1,
    const float* __restrict__ Wq, const float* __restrict__ bq,
    const float* __restrict__ Wk, const float* __restrict__ bk,
    const float* __restrict__ Wv, const float* __restrict__ bv,
    const float* __restrict__ Wo, const float* __restrict__ bo)
{
    extern __shared__ float sm[];
    float* Wq_s = sm;                 // 1536
    float* Wk_s = Wq_s + 1536;        // 1536
    float* Wv_s = Wk_s + 1536;        // 1536
    float* Wo_s = Wv_s + 1536;        // 1536
    float* bq_s = Wo_s + 1536;        // 16
    float* bk_s = bq_s + 16;          // 16
    float* bv_s = bk_s + 16;          // 16
    float* bo_s = bv_s + 16;          // 96
    float* g1_s = bo_s + 96;          // 96
    float* b1_s = g1_s + 96;          // 96
    float* xs   = b1_s + 96;          // 64*97 (padded rows: conflict-free LN)
    float* q_s  = xs + 64*97;         // 64*16
    float* kT_s = q_s + 1024;         // 16*64 (k transposed: coalesced score loop)
    float* v_s  = kT_s + 1024;        // 64*16
    float* sc_s = v_s + 1024;         // 2 * 64*65 (padded)

    const int tid = threadIdx.x;

    for (int i = tid; i < 1536; i += 128) {
        Wq_s[i] = Wq[i]; Wk_s[i] = Wk[i]; Wv_s[i] = Wv[i]; Wo_s[i] = Wo[i];
    }
    for (int i = tid; i < 96; i += 128) { bo_s[i] = bo[i]; g1_s[i] = g1[i]; b1_s[i] = b1[i]; }
    if (tid < 16) { bq_s[tid] = bq[tid]; bk_s[tid] = bk[tid]; bv_s[tid] = bv[tid]; }

    const int wid = blockIdx.x % (NWH * NWW);
    const int bt  = blockIdx.x / (NWH * NWW);          // b*8 + t
    const int wh  = wid / NWW, ww = wid % NWW;
    const int btoff = bt * (H_ * W_ * C_);

    // gather: roll(-4,-4) folded into the index; inverse roll after MSA lands
    // each token back at exactly this same global address.
    for (int idx = tid; idx < NTOK * C_; idx += 128) {
        int n = idx / C_, c = idx - n * C_;
        int i = n >> 3, j = n & 7;
        int h = (wh * 8 + i + 4) & (H_ - 1);
        int w = ww * 8 + j + 4; if (w >= W_) w -= W_;
        xs[n * 97 + c] = x[btoff + (h * W_ + w) * C_ + c];
    }
    __syncthreads();

    // LayerNorm (one thread per token; padded stride -> no bank conflicts)
    if (tid < 64) {
        float* row = xs + tid * 97;
        float mu = 0.f;
        for (int c = 0; c < 96; c++) mu += row[c];
        mu *= (1.f / 96.f);
        float var = 0.f;
        for (int c = 0; c < 96; c++) { float d = row[c] - mu; var += d * d; }
        var *= (1.f / 96.f);
        float rs = rsqrtf(var + EPSF);
        for (int c = 0; c < 96; c++) row[c] = (row[c] - mu) * rs * g1_s[c] + b1_s[c];
    }
    __syncthreads();

    // QKV projections (q,k,v accumulated together to share the x read)
    for (int out = tid; out < NTOK * HK; out += 128) {
        int n = out >> 4, hk = out & 15;
        const float* row = xs + n * 97;
        float aq = bq_s[hk], ak = bk_s[hk], av = bv_s[hk];
        for (int c = 0; c < 96; c++) {
            float xv = row[c];
            aq += xv * Wq_s[c * 16 + hk];
            ak += xv * Wk_s[c * 16 + hk];
            av += xv * Wv_s[c * 16 + hk];
        }
        q_s[n * 16 + hk]  = aq;
        kT_s[hk * 64 + n] = ak;
        v_s[n * 16 + hk]  = av;
    }
    __syncthreads();

    // scores s[h][n][m]
    for (int out = tid; out < NH * NTOK * NTOK; out += 128) {
        int hh = out >> 12;
        int rem = out & 4095;
        int n = rem >> 6, m = rem & 63;
        const float* qp = q_s + n * 16 + hh * 8;
        const float* kp = kT_s + hh * 8 * 64 + m;
        float s = 0.f;
        #pragma unroll
        for (int kk = 0; kk < 8; kk++) s += qp[kk] * kp[kk * 64];
        sc_s[hh * 4160 + n * 65 + m] = s * SCALEF;
    }
    __syncthreads();

    // softmax over m (exactly 128 rows = 128 threads)
    {
        int hh = tid >> 6, n = tid & 63;
        float* p = sc_s + hh * 4160 + n * 65;
        float mx = -1e30f;
        for (int m = 0; m < 64; m++) mx = fmaxf(mx, p[m]);
        float sum = 0.f;
        for (int m = 0; m < 64; m++) { float e = __expf(p[m] - mx); p[m] = e; sum += e; }
        float inv = 1.f / sum;
        for (int m = 0; m < 64; m++) p[m] *= inv;
    }
    __syncthreads();

    // o = A @ V  (store into q_s: q no longer read)
    for (int out = tid; out < NTOK * HK; out += 128) {
        int n = out >> 4, hk = out & 15, hh = hk >> 3;
        const float* pa = sc_s + hh * 4160 + n * 65;
        float a = 0.f;
        for (int m = 0; m < 64; m++) a += pa[m] * v_s[m * 16 + hk];
        q_s[n * 16 + hk] = a;
    }
    __syncthreads();

    // output projection + scatter back (same gathered addresses)
    for (int idx = tid; idx < NTOK * C_; idx += 128) {
        int n = idx / C_, c = idx - n * C_;
        const float* op = q_s + n * 16;
        float y = bo_s[c];
        #pragma unroll
        for (int hk = 0; hk < 16; hk++) y += op[hk] * Wo_s[hk * 96 + c];
        int i = n >> 3, j = n & 7;
        int h = (wh * 8 + i + 4) & (H_ - 1);
        int w = ww * 8 + j + 4; if (w >= W_) w -= W_;
        g_buf1[btoff + (h * W_ + w) * C_ + c] = y;
    }
}

// =====================================================================
// Kernel 2: temporal MSA (T=8 tokens per spatial location)
// grid = B * H * (W/16) = 3072 blocks, 128 threads; 16 locations/block
// =====================================================================
__global__ __launch_bounds__(128) void k_temporal(
    const float* __restrict__ Wq, const float* __restrict__ bq,
    const float* __restrict__ Wk, const float* __restrict__ bk,
    const float* __restrict__ Wv, const float* __restrict__ bv,
    const float* __restrict__ Wo, const float* __restrict__ bo)
{
    extern __shared__ float sm[];
    float* Wq_s = sm;                 // 1536
    float* Wk_s = Wq_s + 1536;
    float* Wv_s = Wk_s + 1536;
    float* Wo_s = Wv_s + 1536;
    float* bq_s = Wo_s + 1536;        // 16
    float* bk_s = bq_s + 16;
    float* bv_s = bk_s + 16;
    float* bo_s = bv_s + 16;          // 96
    float* xt   = bo_s + 96;          // [t][l][c] = 8*16*96 = 12288
    float* q_s  = xt + 12288;         // [l][t][hk] = 2048
    float* kT_s = q_s + 2048;         // [l][hk][t] = 2048
    float* v_s  = kT_s + 2048;        // [l][t][hk] = 2048
    float* sc_s = v_s + 2048;         // [l][h][n][m] = 2048

    const int tid = threadIdx.x;

    for (int i = tid; i < 1536; i += 128) {
        Wq_s[i] = Wq[i]; Wk_s[i] = Wk[i]; Wv_s[i] = Wv[i]; Wo_s[i] = Wo[i];
    }
    for (int i = tid; i < 96; i += 128) bo_s[i] = bo[i];
    if (tid < 16) { bq_s[tid] = bq[tid]; bk_s[tid] = bk[tid]; bv_s[tid] = bv[tid]; }

    const int b   = blockIdx.x / (H_ * (W_ / 16));
    const int rem = blockIdx.x % (H_ * (W_ / 16));
    const int h   = rem / (W_ / 16);
    const int w0  = (rem % (W_ / 16)) * 16;

    // load [8 t][16 w][96 c] — per-t contiguous 1536-float runs
    for (int idx = tid; idx < 8 * 1536; idx += 128) {
        int t = idx / 1536, r = idx - t * 1536;
        xt[idx] = g_buf1[((b * 8 + t) * H_ + h) * W_ * C_ + w0 * C_ + r];
    }
    __syncthreads();

    // QKV
    for (int out = tid; out < 2048; out += 128) {
        int l = out >> 7, r2 = out & 127;
        int t = r2 >> 4, hk = r2 & 15;
        const float* row = xt + t * 1536 + l * 96;
        float aq = bq_s[hk], ak = bk_s[hk], av = bv_s[hk];
        for (int c = 0; c < 96; c++) {
            float xv = row[c];
            aq += xv * Wq_s[c * 16 + hk];
            ak += xv * Wk_s[c * 16 + hk];
            av += xv * Wv_s[c * 16 + hk];
        }
        q_s[l * 128 + t * 16 + hk]  = aq;
        kT_s[l * 128 + hk * 8 + t]  = ak;
        v_s[l * 128 + t * 16 + hk]  = av;
    }
    __syncthreads();

    // scores
    for (int out = tid; out < 2048; out += 128) {
        int l = out >> 7, r2 = out & 127;
        int hh = r2 >> 6, nm = r2 & 63, n = nm >> 3, m = nm & 7;
        const float* qp = q_s + l * 128 + n * 16 + hh * 8;
        const float* kp = kT_s + l * 128 + hh * 64 + m;
        float s = 0.f;
        #pragma unroll
        for (int kk = 0; kk < 8; kk++) s += qp[kk] * kp[kk * 8];
        sc_s[l * 128 + hh * 64 + n * 8 + m] = s * SCALEF;
    }
    __syncthreads();

    // softmax over m (256 rows)
    for (int row = tid; row < 256; row += 128) {
        int l = row >> 4, r2 = row & 15, hh = r2 >> 3, n = r2 & 7;
        float* p = sc_s + l * 128 + hh * 64 + n * 8;
        float mx = -1e30f;
        #pragma unroll
        for (int m = 0; m < 8; m++) mx = fmaxf(mx, p[m]);
        float sum = 0.f;
        #pragma unroll
        for (int m = 0; m < 8; m++) { float e = __expf(p[m] - mx); p[m] = e; sum += e; }
        float inv = 1.f / sum;
        #pragma unroll
        for (int m = 0; m < 8; m++) p[m] *= inv;
    }
    __syncthreads();

    // o = A @ V (into q_s)
    for (int out = tid; out < 2048; out += 128) {
        int l = out >> 7, r2 = out & 127;
        int n = r2 >> 4, hk = r2 & 15, hh = hk >> 3;
        const float* pa = sc_s + l * 128 + hh * 64 + n * 8;
        const float* pv = v_s + l * 128 + hk;
        float a = 0.f;
        #pragma unroll
        for (int m = 0; m < 8; m++) a += pa[m] * pv[m * 16];
        q_s[l * 128 + n * 16 + hk] = a;
    }
    __syncthreads();

    // projection + store (coalesced, same layout as load)
    for (int idx = tid; idx < 8 * 1536; idx += 128) {
        int t = idx / 1536, r = idx - t * 1536;
        int l = r / 96, c = r - l * 96;
        const float* op = q_s + l * 128 + t * 16;
        float y = bo_s[c];
        #pragma unroll
        for (int hk = 0; hk < 16; hk++) y += op[hk] * Wo_s[hk * 96 + c];
        g_buf2[((b * 8 + t) * H_ + h) * W_ * C_ + w0 * C_ + r] = y;
    }
}

// =====================================================================
// Kernel 3: LN2 + MLP (relu(xW1+b) -> relu(.W2+b))
// grid-stride over 6144 tiles of 64 tokens, 256 threads
// =====================================================================
__global__ __launch_bounds__(256) void k_mlp(
    const float* __restrict__ g2, const float* __restrict__ b2,
    const float* __restrict__ W1, const float* __restrict__ b1m,
    const float* __restrict__ W2, const float* __restrict__ b2m,
    float* __restrict__ out)
{
    extern __shared__ float sm[];
    float* W1_s = sm;                 // 9216
    float* W2_s = W1_s + 9216;        // 9216
    float* g_s  = W2_s + 9216;        // 96
    float* bb_s = g_s + 96;           // 96
    float* b1_s = bb_s + 96;          // 96
    float* b2_s = b1_s + 96;          // 96
    float* xn   = b2_s + 96;          // 64*97 (reused for hidden layer)

    const int tid = threadIdx.x;
    for (int i = tid; i < 9216; i += 256) { W1_s[i] = W1[i]; W2_s[i] = W2[i]; }
    if (tid < 96) { g_s[tid] = g2[tid]; bb_s[tid] = b2[tid]; b1_s[tid] = b1m[tid]; b2_s[tid] = b2m[tid]; }
    __syncthreads();

    const int tt   = tid >> 4;          // 0..15
    const int d0   = (tid & 15) * 6;    // 6 output channels
    const int tok0 = tt * 4;            // 4 tokens

    for (int tile = blockIdx.x; tile < NTOTAL / 64; tile += gridDim.x) {
        const float* src = g_buf2 + tile * (64 * 96);
        for (int idx = tid; idx < 6144; idx += 256) {
            int t = idx / 96, c = idx - t * 96;
            xn[t * 97 + c] = src[idx];
        }
        __syncthreads();

        if (tid < 64) {
            float* row = xn + tid * 97;
            float mu = 0.f;
            for (int c = 0; c < 96; c++) mu += row[c];
            mu *= (1.f / 96.f);
            float var = 0.f;
            for (int c = 0; c < 96; c++) { float d = row[c] - mu; var += d * d; }
            var *= (1.f / 96.f);
            float rs = rsqrtf(var + EPSF);
            for (int c = 0; c < 96; c++) row[c] = (row[c] - mu) * rs * g_s[c] + bb_s[c];
        }
        __syncthreads();

        // layer 1: 4 tokens x 6 channels per thread
        float acc[4][6];
        #pragma unroll
        for (int i = 0; i < 4; i++)
            #pragma unroll
            for (int j = 0; j < 6; j++) acc[i][j] = b1_s[d0 + j];
        for (int c = 0; c < 96; c++) {
            float x0 = xn[(tok0 + 0) * 97 + c];
            float x1 = xn[(tok0 + 1) * 97 + c];
            float x2 = xn[(tok0 + 2) * 97 + c];
            float x3 = xn[(tok0 + 3) * 97 + c];
            const float* wr = W1_s + c * 96 + d0;
            #pragma unroll
            for (int j = 0; j < 6; j++) {
                float wv = wr[j];
                acc[0][j] += x0 * wv; acc[1][j] += x1 * wv;
                acc[2][j] += x2 * wv; acc[3][j] += x3 * wv;
            }
        }
        __syncthreads();
        #pragma unroll
        for (int i = 0; i < 4; i++)
            #pragma unroll
            for (int j = 0; j < 6; j++)
                xn[(tok0 + i) * 97 + d0 + j] = fmaxf(acc[i][j], 0.f);
        __syncthreads();

        // layer 2
        #pragma unroll
        for (int i = 0; i < 4; i++)
            #pragma unroll
            for (int j = 0; j < 6; j++) acc[i][j] = b2_s[d0 + j];
        for (int c = 0; c < 96; c++) {
            float x0 = xn[(tok0 + 0) * 97 + c];
            float x1 = xn[(tok0 + 1) * 97 + c];
            float x2 = xn[(tok0 + 2) * 97 + c];
            float x3 = xn[(tok0 + 3) * 97 + c];
            const float* wr = W2_s + c * 96 + d0;
            #pragma unroll
            for (int j = 0; j < 6; j++) {
                float wv = wr[j];
                acc[0][j] += x0 * wv; acc[1][j] += x1 * wv;
                acc[2][j] += x2 * wv; acc[3][j] += x3 * wv;
            }
        }
        float* dst = out + tile * 6144;
        #pragma unroll
        for (int i = 0; i < 4; i++)
            #pragma unroll
            for (int j = 0; j < 6; j++)
                dst[(tok0 + i) * 96 + d0 + j] = fmaxf(acc[i][j], 0.f);
        __syncthreads();
    }
}

// =====================================================================
extern "C" void kernel_launch(void* const* d_in, const int* in_sizes, int n_in,
                              void* d_out, int out_size)
{
    const float* x   = (const float*)d_in[0];
    const float* g1  = (const float*)d_in[1];
    const float* b1  = (const float*)d_in[2];
    const float* g2  = (const float*)d_in[3];
    const float* b2  = (const float*)d_in[4];
    const float* Wq  = (const float*)d_in[5];
    const float* bq  = (const float*)d_in[6];
    const float* Wk  = (const float*)d_in[7];
    const float* bk  = (const float*)d_in[8];
    const float* Wv  = (const float*)d_in[9];
    const float* bv  = (const float*)d_in[10];
    const float* Wo  = (const float*)d_in[11];
    const float* bo  = (const float*)d_in[12];
    const float* W1  = (const float*)d_in[13];
    const float* b1m = (const float*)d_in[14];
    const float* W2  = (const float*)d_in[15];
    const float* b2m = (const float*)d_in[16];
    float* out = (float*)d_out;

    cudaFuncSetAttribute(k_spatial,  cudaFuncAttributeMaxDynamicSharedMemorySize, 96320);
    cudaFuncSetAttribute(k_temporal, cudaFuncAttributeMaxDynamicSharedMemorySize, 107072);
    cudaFuncSetAttribute(k_mlp,      cudaFuncAttributeMaxDynamicSharedMemorySize, 100096);

    k_spatial<<<B_ * T_ * NWH * NWW, 128, 96320>>>(x, g1, b1, Wq, bq, Wk, bk, Wv, bv, Wo, bo);
    k_temporal<<<B_ * H_ * (W_ / 16), 128, 107072>>>(Wq, bq, Wk, bk, Wv, bv, Wo, bo);
    k_mlp<<<1536, 256, 100096>>>(g2, b2, W1, b1m, W2, b2m, out);
}

// round 2
// speedup vs baseline: 1.5593x; 1.5593x over previous
#include <cuda_runtime.h>

namespace cfg {
constexpr int B_ = 2, T_ = 8, H_ = 128, W_ = 192, C_ = 96;
constexpr int NWH = 16, NWW = 24;
constexpr int NTOTAL = B_ * T_ * H_ * W_;
}
using namespace cfg;

__device__ float g_buf1[B_*T_*H_*W_*C_];
__device__ float g_buf2[B_*T_*H_*W_*C_];

#define SCALEF 0.35355339059327373f
#define EPSF   1e-3f

// =====================================================================
// Kernel 1: LN1 + shifted-window spatial MSA  (6144 blocks, 128 thr)
// smem 63296 B -> 3 blocks/SM
// =====================================================================
__global__ __launch_bounds__(128) void k_spatial(
    const float* __restrict__ x,
    const float* __restrict__ g1, const float* __restrict__ b1,
    const float* __restrict__ Wq, const float* __restrict__ bq,
    const float* __restrict__ Wk, const float* __restrict__ bk,
    const float* __restrict__ Wv, const float* __restrict__ bv,
    const float* __restrict__ Wo, const float* __restrict__ bo)
{
    extern __shared__ float sm[];
    float* Wq_s  = sm;            // [c][16]
    float* Wk_s  = sm + 1536;
    float* Wv_s  = sm + 3072;
    float* WoT_s = sm + 4608;     // [c][16] transposed
    float* bq_s  = sm + 6144;
    float* bk_s  = sm + 6160;
    float* bv_s  = sm + 6176;
    float* bo_s  = sm + 6192;     // 96
    float* g1_s  = sm + 6288;     // 96
    float* b1_s  = sm + 6384;     // 96
    float* xs    = sm + 6480;     // 64 x 97
    float* k_s   = sm + 12688;    // 64 x 16
    float* v_s   = sm + 13712;    // 64 x 16
    float* o_s   = sm + 14736;    // 64 x 17

    const int tid  = threadIdx.x;
    const int n    = tid & 63;     // token
    const int half = tid >> 6;     // head
    const int lane = tid & 31;
    const int warp = tid >> 5;

    for (int i = tid; i < 1536; i += 128) {
        Wq_s[i] = Wq[i]; Wk_s[i] = Wk[i]; Wv_s[i] = Wv[i];
        WoT_s[i] = Wo[(i & 15) * 96 + (i >> 4)];
    }
    for (int i = tid; i < 96; i += 128) { bo_s[i] = bo[i]; g1_s[i] = g1[i]; b1_s[i] = b1[i]; }
    if (tid < 16) { bq_s[tid] = bq[tid]; bk_s[tid] = bk[tid]; bv_s[tid] = bv[tid]; }

    const int wid = blockIdx.x % (NWH * NWW);
    const int bt  = blockIdx.x / (NWH * NWW);
    const int wh  = wid / NWW, ww = wid % NWW;
    const int btoff = bt * (H_ * W_ * C_);

    // gather (roll folded into index), float4 global loads
    for (int idx = tid; idx < 1536; idx += 128) {
        int r = idx / 24, c4 = (idx - r * 24) * 4;
        int i = r >> 3, j = r & 7;
        int h = (wh * 8 + i + 4) & (H_ - 1);
        int w = ww * 8 + j + 4; if (w >= W_) w -= W_;
        float4 vv = *(const float4*)&x[btoff + (h * W_ + w) * C_ + c4];
        float* row = xs + r * 97 + c4;
        row[0] = vv.x; row[1] = vv.y; row[2] = vv.z; row[3] = vv.w;
    }
    __syncthreads();

    // warp-shuffle LayerNorm: each warp handles 16 tokens
    for (int t = warp * 16; t < warp * 16 + 16; t++) {
        float* row = xs + t * 97;
        float a0 = row[lane], a1 = row[lane + 32], a2 = row[lane + 64];
        float s  = a0 + a1 + a2;
        float s2 = a0 * a0 + a1 * a1 + a2 * a2;
        #pragma unroll
        for (int off = 16; off > 0; off >>= 1) {
            s  += __shfl_xor_sync(0xffffffff, s,  off);
            s2 += __shfl_xor_sync(0xffffffff, s2, off);
        }
        float mu = s * (1.f / 96.f);
        float var = s2 * (1.f / 96.f) - mu * mu;
        float rs = rsqrtf(var + EPSF);
        row[lane]      = (a0 - mu) * rs * g1_s[lane]      + b1_s[lane];
        row[lane + 32] = (a1 - mu) * rs * g1_s[lane + 32] + b1_s[lane + 32];
        row[lane + 64] = (a2 - mu) * rs * g1_s[lane + 64] + b1_s[lane + 64];
    }
    __syncthreads();

    // QKV: thread computes 8 q/k/v outputs for token n, head `half`
    float aq[8], ak[8], av[8];
    {
        const int hk0 = half * 8;
        #pragma unroll
        for (int j = 0; j < 8; j++) { aq[j] = bq_s[hk0+j]; ak[j] = bk_s[hk0+j]; av[j] = bv_s[hk0+j]; }
        const float* row = xs + n * 97;
        for (int c = 0; c < 96; c++) {
            float xv = row[c];
            float4 wq0 = *(const float4*)&Wq_s[c*16 + hk0];
            float4 wq1 = *(const float4*)&Wq_s[c*16 + hk0 + 4];
            float4 wk0 = *(const float4*)&Wk_s[c*16 + hk0];
            float4 wk1 = *(const float4*)&Wk_s[c*16 + hk0 + 4];
            float4 wv0 = *(const float4*)&Wv_s[c*16 + hk0];
            float4 wv1 = *(const float4*)&Wv_s[c*16 + hk0 + 4];
            aq[0] += xv*wq0.x; aq[1] += xv*wq0.y; aq[2] += xv*wq0.z; aq[3] += xv*wq0.w;
            aq[4] += xv*wq1.x; aq[5] += xv*wq1.y; aq[6] += xv*wq1.z; aq[7] += xv*wq1.w;
            ak[0] += xv*wk0.x; ak[1] += xv*wk0.y; ak[2] += xv*wk0.z; ak[3] += xv*wk0.w;
            ak[4] += xv*wk1.x; ak[5] += xv*wk1.y; ak[6] += xv*wk1.z; ak[7] += xv*wk1.w;
            av[0] += xv*wv0.x; av[1] += xv*wv0.y; av[2] += xv*wv0.z; av[3] += xv*wv0.w;
            av[4] += xv*wv1.x; av[5] += xv*wv1.y; av[6] += xv*wv1.z; av[7] += xv*wv1.w;
        }
        *(float4*)&k_s[n*16 + hk0]     = make_float4(ak[0],ak[1],ak[2],ak[3]);
        *(float4*)&k_s[n*16 + hk0 + 4] = make_float4(ak[4],ak[5],ak[6],ak[7]);
        *(float4*)&v_s[n*16 + hk0]     = make_float4(av[0],av[1],av[2],av[3]);
        *(float4*)&v_s[n*16 + hk0 + 4] = make_float4(av[4],av[5],av[6],av[7]);
    }
    __syncthreads();

    // attention for (head=half, query=n); q in regs, k/v broadcast loads.
    // scores are tiny (|s|<~2): plain exp is numerically safe.
    {
        const int hk0 = half * 8;
        float o[8] = {0,0,0,0,0,0,0,0};
        float lsum = 0.f;
        for (int m = 0; m < 64; m++) {
            float4 k0 = *(const float4*)&k_s[m*16 + hk0];
            float4 k1 = *(const float4*)&k_s[m*16 + hk0 + 4];
            float s = aq[0]*k0.x + aq[1]*k0.y + aq[2]*k0.z + aq[3]*k0.w
                    + aq[4]*k1.x + aq[5]*k1.y + aq[6]*k1.z + aq[7]*k1.w;
            float p = __expf(s * SCALEF);
            lsum += p;
            float4 v0 = *(const float4*)&v_s[m*16 + hk0];
            float4 v1 = *(const float4*)&v_s[m*16 + hk0 + 4];
            o[0] += p*v0.x; o[1] += p*v0.y; o[2] += p*v0.z; o[3] += p*v0.w;
            o[4] += p*v1.x; o[5] += p*v1.y; o[6] += p*v1.z; o[7] += p*v1.w;
        }
        float inv = 1.f / lsum;
        #pragma unroll
        for (int j = 0; j < 8; j++) o_s[n*17 + hk0 + j] = o[j] * inv;
    }
    __syncthreads();

    // output projection: thread (n, half) -> 48 channels; write into xs
    {
        float orr[16];
        #pragma unroll
        for (int j = 0; j < 16; j++) orr[j] = o_s[n*17 + j];
        const int c0 = half * 48;
        for (int cc = 0; cc < 48; cc++) {
            int c = c0 + cc;
            const float4* wp = (const float4*)&WoT_s[c*16];
            float4 w0 = wp[0], w1 = wp[1], w2 = wp[2], w3 = wp[3];
            float y = bo_s[c];
            y += orr[0]*w0.x + orr[1]*w0.y + orr[2]*w0.z + orr[3]*w0.w;
            y += orr[4]*w1.x + orr[5]*w1.y + orr[6]*w1.z + orr[7]*w1.w;
            y += orr[8]*w2.x + orr[9]*w2.y + orr[10]*w2.z + orr[11]*w2.w;
            y += orr[12]*w3.x + orr[13]*w3.y + orr[14]*w3.z + orr[15]*w3.w;
            xs[n*97 + c] = y;
        }
    }
    __syncthreads();

    // scatter back, float4 global stores
    for (int idx = tid; idx < 1536; idx += 128) {
        int r = idx / 24, c4 = (idx - r * 24) * 4;
        int i = r >> 3, j = r & 7;
        int h = (wh * 8 + i + 4) & (H_ - 1);
        int w = ww * 8 + j + 4; if (w >= W_) w -= W_;
        const float* row = xs + r * 97 + c4;
        *(float4*)&g_buf1[btoff + (h * W_ + w) * C_ + c4] =
            make_float4(row[0], row[1], row[2], row[3]);
    }
}

// =====================================================================
// Kernel 2: temporal MSA, 8 locations/block (6144 blocks, 128 thr)
// smem 63040 B -> 3 blocks/SM
// =====================================================================
__global__ __launch_bounds__(128) void k_temporal(
    const float* __restrict__ Wq, const float* __restrict__ bq,
    const float* __restrict__ Wk, const float* __restrict__ bk,
    const float* __restrict__ Wv, const float* __restrict__ bv,
    const float* __restrict__ Wo, const float* __restrict__ bo)
{
    extern __shared__ float sm[];
    float* Wq_s  = sm;
    float* Wk_s  = sm + 1536;
    float* Wv_s  = sm + 3072;
    float* WoT_s = sm + 4608;
    float* bq_s  = sm + 6144;
    float* bk_s  = sm + 6160;
    float* bv_s  = sm + 6176;
    float* bo_s  = sm + 6192;    // 96
    float* xs    = sm + 6288;    // 64 x 97 (row = l*8 + t)
    float* k_s   = sm + 12496;   // 8 locations x 136
    float* v_s   = sm + 13584;   // 8 x 136
    float* o_s   = sm + 14672;   // 64 x 17

    const int tid  = threadIdx.x;
    const int n    = tid & 63;    // row = l*8+t
    const int half = tid >> 6;
    const int l    = n >> 3, t = n & 7;

    for (int i = tid; i < 1536; i += 128) {
        Wq_s[i] = Wq[i]; Wk_s[i] = Wk[i]; Wv_s[i] = Wv[i];
        WoT_s[i] = Wo[(i & 15) * 96 + (i >> 4)];
    }
    for (int i = tid; i < 96; i += 128) bo_s[i] = bo[i];
    if (tid < 16) { bq_s[tid] = bq[tid]; bk_s[tid] = bk[tid]; bv_s[tid] = bv[tid]; }

    const int b   = blockIdx.x / (H_ * 24);
    const int rem = blockIdx.x % (H_ * 24);
    const int h   = rem / 24;
    const int w0  = (rem % 24) * 8;

    for (int idx = tid; idx < 1536; idx += 128) {
        int r = idx / 24, c4 = (idx - r * 24) * 4;
        int rl = r >> 3, rt = r & 7;
        float4 vv = *(const float4*)&g_buf1[((b*8 + rt)*H_ + h)*(W_*C_) + (w0 + rl)*C_ + c4];
        float* row = xs + r * 97 + c4;
        row[0] = vv.x; row[1] = vv.y; row[2] = vv.z; row[3] = vv.w;
    }
    __syncthreads();

    // QKV
    float aq[8];
    {
        const int hk0 = half * 8;
        float ak[8], av[8];
        #pragma unroll
        for (int j = 0; j < 8; j++) { aq[j] = bq_s[hk0+j]; ak[j] = bk_s[hk0+j]; av[j] = bv_s[hk0+j]; }
        const float* row = xs + n * 97;
        for (int c = 0; c < 96; c++) {
            float xv = row[c];
            float4 wq0 = *(const float4*)&Wq_s[c*16 + hk0];
            float4 wq1 = *(const float4*)&Wq_s[c*16 + hk0 + 4];
            float4 wk0 = *(const float4*)&Wk_s[c*16 + hk0];
            float4 wk1 = *(const float4*)&Wk_s[c*16 + hk0 + 4];
            float4 wv0 = *(const float4*)&Wv_s[c*16 + hk0];
            float4 wv1 = *(const float4*)&Wv_s[c*16 + hk0 + 4];
            aq[0] += xv*wq0.x; aq[1] += xv*wq0.y; aq[2] += xv*wq0.z; aq[3] += xv*wq0.w;
            aq[4] += xv*wq1.x; aq[5] += xv*wq1.y; aq[6] += xv*wq1.z; aq[7] += xv*wq1.w;
            ak[0] += xv*wk0.x; ak[1] += xv*wk0.y; ak[2] += xv*wk0.z; ak[3] += xv*wk0.w;
            ak[4] += xv*wk1.x; ak[5] += xv*wk1.y; ak[6] += xv*wk1.z; ak[7] += xv*wk1.w;
            av[0] += xv*wv0.x; av[1] += xv*wv0.y; av[2] += xv*wv0.z; av[3] += xv*wv0.w;
            av[4] += xv*wv1.x; av[5] += xv*wv1.y; av[6] += xv*wv1.z; av[7] += xv*wv1.w;
        }
        *(float4*)&k_s[l*136 + t*16 + hk0]     = make_float4(ak[0],ak[1],ak[2],ak[3]);
        *(float4*)&k_s[l*136 + t*16 + hk0 + 4] = make_float4(ak[4],ak[5],ak[6],ak[7]);
        *(float4*)&v_s[l*136 + t*16 + hk0]     = make_float4(av[0],av[1],av[2],av[3]);
        *(float4*)&v_s[l*136 + t*16 + hk0 + 4] = make_float4(av[4],av[5],av[6],av[7]);
    }
    __syncthreads();

    // attention over T=8 within location l
    {
        const int hk0 = half * 8;
        float o[8] = {0,0,0,0,0,0,0,0};
        float lsum = 0.f;
        #pragma unroll
        for (int m = 0; m < 8; m++) {
            float4 k0 = *(const float4*)&k_s[l*136 + m*16 + hk0];
            float4 k1 = *(const float4*)&k_s[l*136 + m*16 + hk0 + 4];
            float s = aq[0]*k0.x + aq[1]*k0.y + aq[2]*k0.z + aq[3]*k0.w
                    + aq[4]*k1.x + aq[5]*k1.y + aq[6]*k1.z + aq[7]*k1.w;
            float p = __expf(s * SCALEF);
            lsum += p;
            float4 v0 = *(const float4*)&v_s[l*136 + m*16 + hk0];
            float4 v1 = *(const float4*)&v_s[l*136 + m*16 + hk0 + 4];
            o[0] += p*v0.x; o[1] += p*v0.y; o[2] += p*v0.z; o[3] += p*v0.w;
            o[4] += p*v1.x; o[5] += p*v1.y; o[6] += p*v1.z; o[7] += p*v1.w;
        }
        float inv = 1.f / lsum;
        #pragma unroll
        for (int j = 0; j < 8; j++) o_s[n*17 + hk0 + j] = o[j] * inv;
    }
    __syncthreads();

    // projection
    {
        float orr[16];
        #pragma unroll
        for (int j = 0; j < 16; j++) orr[j] = o_s[n*17 + j];
        const int c0 = half * 48;
        for (int cc = 0; cc < 48; cc++) {
            int c = c0 + cc;
            const float4* wp = (const float4*)&WoT_s[c*16];
            float4 w0 = wp[0], w1 = wp[1], w2 = wp[2], w3 = wp[3];
            float y = bo_s[c];
            y += orr[0]*w0.x + orr[1]*w0.y + orr[2]*w0.z + orr[3]*w0.w;
            y += orr[4]*w1.x + orr[5]*w1.y + orr[6]*w1.z + orr[7]*w1.w;
            y += orr[8]*w2.x + orr[9]*w2.y + orr[10]*w2.z + orr[11]*w2.w;
            y += orr[12]*w3.x + orr[13]*w3.y + orr[14]*w3.z + orr[15]*w3.w;
            xs[n*97 + c] = y;
        }
    }
    __syncthreads();

    for (int idx = tid; idx < 1536; idx += 128) {
        int r = idx / 24, c4 = (idx - r * 24) * 4;
        int rl = r >> 3, rt = r & 7;
        const float* row = xs + r * 97 + c4;
        *(float4*)&g_buf2[((b*8 + rt)*H_ + h)*(W_*C_) + (w0 + rl)*C_ + c4] =
            make_float4(row[0], row[1], row[2], row[3]);
    }
}

// =====================================================================
// Kernel 3: LN2 + MLP  (592 blocks, 256 thr, grid-stride over 6144 tiles)
// =====================================================================
__global__ __launch_bounds__(256) void k_mlp(
    const float* __restrict__ g2, const float* __restrict__ b2,
    const float* __restrict__ W1, const float* __restrict__ b1m,
    const float* __restrict__ W2, const float* __restrict__ b2m,
    float* __restrict__ out)
{
    extern __shared__ float sm[];
    float* W1_s = sm;                 // 9216
    float* W2_s = W1_s + 9216;        // 9216
    float* g_s  = W2_s + 9216;        // 96
    float* bb_s = g_s + 96;
    float* b1_s = bb_s + 96;
    float* b2_s = b1_s + 96;
    float* xn   = b2_s + 96;          // 64 x 97

    const int tid = threadIdx.x;
    const int lane = tid & 31, warp = tid >> 5;
    for (int i = tid; i < 2304; i += 256) {
        ((float4*)W1_s)[i] = ((const float4*)W1)[i];
        ((float4*)W2_s)[i] = ((const float4*)W2)[i];
    }
    if (tid < 96) { g_s[tid] = g2[tid]; bb_s[tid] = b2[tid]; b1_s[tid] = b1m[tid]; b2_s[tid] = b2m[tid]; }
    __syncthreads();

    const int tt   = tid >> 4;
    const int d0   = (tid & 15) * 6;
    const int tok0 = tt * 4;

    for (int tile = blockIdx.x; tile < NTOTAL / 64; tile += gridDim.x) {
        const float* src = g_buf2 + tile * 6144;
        for (int idx = tid; idx < 1536; idx += 256) {
            int t = idx / 24, c4 = (idx - t * 24) * 4;
            float4 vv = *(const float4*)&src[t * 96 + c4];
            float* row = xn + t * 97 + c4;
            row[0] = vv.x; row[1] = vv.y; row[2] = vv.z; row[3] = vv.w;
        }
        __syncthreads();

        // warp-shuffle LN: each of 8 warps handles 8 tokens
        for (int t = warp * 8; t < warp * 8 + 8; t++) {
            float* row = xn + t * 97;
            float a0 = row[lane], a1 = row[lane + 32], a2 = row[lane + 64];
            float s  = a0 + a1 + a2;
            float s2 = a0*a0 + a1*a1 + a2*a2;
            #pragma unroll
            for (int off = 16; off > 0; off >>= 1) {
                s  += __shfl_xor_sync(0xffffffff, s,  off);
                s2 += __shfl_xor_sync(0xffffffff, s2, off);
            }
            float mu = s * (1.f/96.f);
            float var = s2 * (1.f/96.f) - mu * mu;
            float rs = rsqrtf(var + EPSF);
            row[lane]      = (a0 - mu) * rs * g_s[lane]      + bb_s[lane];
            row[lane + 32] = (a1 - mu) * rs * g_s[lane + 32] + bb_s[lane + 32];
            row[lane + 64] = (a2 - mu) * rs * g_s[lane + 64] + bb_s[lane + 64];
        }
        __syncthreads();

        float acc[4][6];
        #pragma unroll
        for (int i = 0; i < 4; i++)
            #pragma unroll
            for (int j = 0; j < 6; j++) acc[i][j] = b1_s[d0 + j];
        for (int c = 0; c < 96; c++) {
            float x0 = xn[(tok0 + 0) * 97 + c];
            float x1 = xn[(tok0 + 1) * 97 + c];
            float x2 = xn[(tok0 + 2) * 97 + c];
            float x3 = xn[(tok0 + 3) * 97 + c];
            const float* wr = W1_s + c * 96 + d0;
            #pragma unroll
            for (int j = 0; j < 6; j++) {
                float wv = wr[j];
                acc[0][j] += x0 * wv; acc[1][j] += x1 * wv;
                acc[2][j] += x2 * wv; acc[3][j] += x3 * wv;
            }
        }
        __syncthreads();
        #pragma unroll
        for (int i = 0; i < 4; i++)
            #pragma unroll
            for (int j = 0; j < 6; j++)
                xn[(tok0 + i) * 97 + d0 + j] = fmaxf(acc[i][j], 0.f);
        __syncthreads();

        #pragma unroll
        for (int i = 0; i < 4; i++)
            #pragma unroll
            for (int j = 0; j < 6; j++) acc[i][j] = b2_s[d0 + j];
        for (int c = 0; c < 96; c++) {
            float x0 = xn[(tok0 + 0) * 97 + c];
            float x1 = xn[(tok0 + 1) * 97 + c];
            float x2 = xn[(tok0 + 2) * 97 + c];
            float x3 = xn[(tok0 + 3) * 97 + c];
            const float* wr = W2_s + c * 96 + d0;
            #pragma unroll
            for (int j = 0; j < 6; j++) {
                float wv = wr[j];
                acc[0][j] += x0 * wv; acc[1][j] += x1 * wv;
                acc[2][j] += x2 * wv; acc[3][j] += x3 * wv;
            }
        }
        float* dst = out + tile * 6144;
        #pragma unroll
        for (int i = 0; i < 4; i++)
            #pragma unroll
            for (int j = 0; j < 6; j++)
                dst[(tok0 + i) * 96 + d0 + j] = fmaxf(acc[i][j], 0.f);
        __syncthreads();
    }
}

// =====================================================================
extern "C" void kernel_launch(void* const* d_in, const int* in_sizes, int n_in,
                              void* d_out, int out_size)
{
    const float* x   = (const float*)d_in[0];
    const float* g1  = (const float*)d_in[1];
    const float* b1  = (const float*)d_in[2];
    const float* g2  = (const float*)d_in[3];
    const float* b2  = (const float*)d_in[4];
    const float* Wq  = (const float*)d_in[5];
    const float* bq  = (const float*)d_in[6];
    const float* Wk  = (const float*)d_in[7];
    const float* bk  = (const float*)d_in[8];
    const float* Wv  = (const float*)d_in[9];
    const float* bv  = (const float*)d_in[10];
    const float* Wo  = (const float*)d_in[11];
    const float* bo  = (const float*)d_in[12];
    const float* W1  = (const float*)d_in[13];
    const float* b1m = (const float*)d_in[14];
    const float* W2  = (const float*)d_in[15];
    const float* b2m = (const float*)d_in[16];
    float* out = (float*)d_out;

    cudaFuncSetAttribute(k_spatial,  cudaFuncAttributeMaxDynamicSharedMemorySize, 63296);
    cudaFuncSetAttribute(k_temporal, cudaFuncAttributeMaxDynamicSharedMemorySize, 63040);
    cudaFuncSetAttribute(k_mlp,      cudaFuncAttributeMaxDynamicSharedMemorySize, 100096);

    k_spatial<<<B_ * T_ * NWH * NWW, 128, 63296>>>(x, g1, b1, Wq, bq, Wk, bk, Wv, bv, Wo, bo);
    k_temporal<<<B_ * H_ * 24, 128, 63040>>>(Wq, bq, Wk, bk, Wv, bv, Wo, bo);
    k_mlp<<<592, 256, 100096>>>(g2, b2, W1, b1m, W2, b2m, out);
}

// round 4
// speedup vs baseline: 1.7380x; 1.1146x over previous
#include <cuda_runtime.h>

namespace cfg {
constexpr int B_ = 2, T_ = 8, H_ = 128, W_ = 192, C_ = 96;
constexpr int NWH = 16, NWW = 24;
constexpr int NTOTAL = B_ * T_ * H_ * W_;
}
using namespace cfg;

__device__ float g_buf1[B_*T_*H_*W_*C_];
__device__ float g_buf2[B_*T_*H_*W_*C_];

#define SCALEF 0.35355339059327373f
#define EPSF   1e-3f

__device__ __forceinline__ void acc8(float* a, float x, float4 w0, float4 w1) {
    a[0] += x*w0.x; a[1] += x*w0.y; a[2] += x*w0.z; a[3] += x*w0.w;
    a[4] += x*w1.x; a[5] += x*w1.y; a[6] += x*w1.z; a[7] += x*w1.w;
}
__device__ __forceinline__ float dot8(const float* a, float4 k0, float4 k1) {
    return a[0]*k0.x + a[1]*k0.y + a[2]*k0.z + a[3]*k0.w
         + a[4]*k1.x + a[5]*k1.y + a[6]*k1.z + a[7]*k1.w;
}

// tf32 helpers for 3xTF32 fp32-accurate mma
__device__ __forceinline__ void split_tf32(float x, unsigned& hi, unsigned& lo) {
    unsigned h; asm("cvt.rna.tf32.f32 %0,%1;" : "=r"(h) : "f"(x));
    float hf = __uint_as_float(h);
    asm("cvt.rna.tf32.f32 %0,%1;" : "=r"(lo) : "f"(x - hf));
    hi = h;
}
__device__ __forceinline__ void mma8(float* d, const unsigned* a, unsigned b0, unsigned b1) {
    asm volatile("mma.sync.aligned.m16n8k8.row.col.f32.tf32.tf32.f32 "
        "{%0,%1,%2,%3},{%4,%5,%6,%7},{%8,%9},{%0,%1,%2,%3};"
        : "+f"(d[0]), "+f"(d[1]), "+f"(d[2]), "+f"(d[3])
        : "r"(a[0]), "r"(a[1]), "r"(a[2]), "r"(a[3]), "r"(b0), "r"(b1));
}

// =====================================================================
// Kernel 1: LN1 + shifted-window spatial MSA
// 2 windows per block, 3072 blocks, 128 threads. smem 104768 B.
// thread = (window wi, head half, pair p) -> tokens p and p+32
// =====================================================================
__global__ __launch_bounds__(128) void k_spatial(
    const float* __restrict__ x,
    const float* __restrict__ g1, const float* __restrict__ b1,
    const float* __restrict__ Wq, const float* __restrict__ bq,
    const float* __restrict__ Wk, const float* __restrict__ bk,
    const float* __restrict__ Wv, const float* __restrict__ bv,
    const float* __restrict__ Wo, const float* __restrict__ bo)
{
    extern __shared__ float sm[];
    float* Wq_s  = sm;            // [c][16]
    float* Wk_s  = sm + 1536;
    float* Wv_s  = sm + 3072;
    float* WoT_s = sm + 4608;     // [c][16]
    float* bq_s  = sm + 6144;
    float* bk_s  = sm + 6160;
    float* bv_s  = sm + 6176;
    float* bo_s  = sm + 6192;
    float* g1_s  = sm + 6288;
    float* b1_s  = sm + 6384;
    float* xs    = sm + 6480;     // 2 x (64 x 97)
    float* k_sb  = sm + 18896;    // 2 x (64 x 20)
    float* v_sb  = sm + 21456;    // 2 x (64 x 20)
    float* o_sb  = sm + 24016;    // 2 x (64 x 17)

    const int tid  = threadIdx.x;
    const int wi   = tid >> 6;          // window in block
    const int half = (tid >> 5) & 1;    // head
    const int p    = tid & 31;          // pair id
    const int lane = tid & 31;
    const int warp = tid >> 5;
    const int hk0  = half * 8;

    for (int i = tid; i < 1536; i += 128) {
        Wq_s[i] = Wq[i]; Wk_s[i] = Wk[i]; Wv_s[i] = Wv[i];
        WoT_s[i] = Wo[(i & 15) * 96 + (i >> 4)];
    }
    for (int i = tid; i < 96; i += 128) { bo_s[i] = bo[i]; g1_s[i] = g1[i]; b1_s[i] = b1[i]; }
    if (tid < 16) { bq_s[tid] = bq[tid]; bk_s[tid] = bk[tid]; bv_s[tid] = bv[tid]; }

    const int bt   = (2 * blockIdx.x) / (NWH * NWW);
    const int wid0 = (2 * blockIdx.x) % (NWH * NWW);
    const int btoff = bt * (H_ * W_ * C_);

    // gather both windows (roll folded in), float4 loads
    for (int idx = tid; idx < 3072; idx += 128) {
        int wv2, rem;
        if (idx >= 1536) { wv2 = 1; rem = idx - 1536; } else { wv2 = 0; rem = idx; }
        int r = rem / 24, c4 = (rem - r * 24) * 4;
        int wid = wid0 + wv2;
        int wh = wid / NWW, ww = wid % NWW;
        int i = r >> 3, j = r & 7;
        int h = (wh * 8 + i + 4) & (H_ - 1);
        int w = ww * 8 + j + 4; if (w >= W_) w -= W_;
        float4 vv = *(const float4*)&x[btoff + (h * W_ + w) * C_ + c4];
        float* row = xs + wv2 * 6208 + r * 97 + c4;
        row[0] = vv.x; row[1] = vv.y; row[2] = vv.z; row[3] = vv.w;
    }
    __syncthreads();

    // warp-shuffle LN over 128 rows (2 windows x 64)
    for (int r = warp * 32; r < warp * 32 + 32; r++) {
        float* row = xs + (r >> 6) * 6208 + (r & 63) * 97;
        float a0 = row[lane], a1 = row[lane + 32], a2 = row[lane + 64];
        float s  = a0 + a1 + a2;
        float s2 = a0*a0 + a1*a1 + a2*a2;
        #pragma unroll
        for (int off = 16; off > 0; off >>= 1) {
            s  += __shfl_xor_sync(0xffffffff, s,  off);
            s2 += __shfl_xor_sync(0xffffffff, s2, off);
        }
        float mu = s * (1.f / 96.f);
        float var = s2 * (1.f / 96.f) - mu * mu;
        float rs = rsqrtf(var + EPSF);
        row[lane]      = (a0 - mu) * rs * g1_s[lane]      + b1_s[lane];
        row[lane + 32] = (a1 - mu) * rs * g1_s[lane + 32] + b1_s[lane + 32];
        row[lane + 64] = (a2 - mu) * rs * g1_s[lane + 64] + b1_s[lane + 64];
    }
    __syncthreads();

    float* xsw  = xs   + wi * 6208;
    float* k_sw = k_sb + wi * 1280;
    float* v_sw = v_sb + wi * 1280;
    float* o_sw = o_sb + wi * 1088;
    const int n0 = p, n1 = p + 32;

    // QKV for 2 tokens, one head (weights amortized over 2 tokens)
    float aq0[8], aq1[8];
    {
        float ak0[8], ak1[8], av0[8], av1[8];
        #pragma unroll
        for (int j = 0; j < 8; j++) {
            aq0[j] = bq_s[hk0+j]; aq1[j] = bq_s[hk0+j];
            ak0[j] = bk_s[hk0+j]; ak1[j] = bk_s[hk0+j];
            av0[j] = bv_s[hk0+j]; av1[j] = bv_s[hk0+j];
        }
        for (int c = 0; c < 96; c++) {
            float x0 = xsw[n0 * 97 + c];
            float x1 = xsw[n1 * 97 + c];
            float4 wq0 = *(const float4*)&Wq_s[c*16 + hk0];
            float4 wq1 = *(const float4*)&Wq_s[c*16 + hk0 + 4];
            acc8(aq0, x0, wq0, wq1); acc8(aq1, x1, wq0, wq1);
            float4 wk0 = *(const float4*)&Wk_s[c*16 + hk0];
            float4 wk1 = *(const float4*)&Wk_s[c*16 + hk0 + 4];
            acc8(ak0, x0, wk0, wk1); acc8(ak1, x1, wk0, wk1);
            float4 wv0 = *(const float4*)&Wv_s[c*16 + hk0];
            float4 wv1 = *(const float4*)&Wv_s[c*16 + hk0 + 4];
            acc8(av0, x0, wv0, wv1); acc8(av1, x1, wv0, wv1);
        }
        *(float4*)&k_sw[n0*20 + hk0]     = make_float4(ak0[0],ak0[1],ak0[2],ak0[3]);
        *(float4*)&k_sw[n0*20 + hk0 + 4] = make_float4(ak0[4],ak0[5],ak0[6],ak0[7]);
        *(float4*)&k_sw[n1*20 + hk0]     = make_float4(ak1[0],ak1[1],ak1[2],ak1[3]);
        *(float4*)&k_sw[n1*20 + hk0 + 4] = make_float4(ak1[4],ak1[5],ak1[6],ak1[7]);
        *(float4*)&v_sw[n0*20 + hk0]     = make_float4(av0[0],av0[1],av0[2],av0[3]);
        *(float4*)&v_sw[n0*20 + hk0 + 4] = make_float4(av0[4],av0[5],av0[6],av0[7]);
        *(float4*)&v_sw[n1*20 + hk0]     = make_float4(av1[0],av1[1],av1[2],av1[3]);
        *(float4*)&v_sw[n1*20 + hk0 + 4] = make_float4(av1[4],av1[5],av1[6],av1[7]);
    }
    __syncthreads();

    // attention: 2 queries share every k/v load (broadcast within warp)
    {
        float o0[8] = {0,0,0,0,0,0,0,0}, o1[8] = {0,0,0,0,0,0,0,0};
        float l0 = 0.f, l1 = 0.f;
        for (int m = 0; m < 64; m++) {
            float4 k0 = *(const float4*)&k_sw[m*20 + hk0];
            float4 k1 = *(const float4*)&k_sw[m*20 + hk0 + 4];
            float s0 = dot8(aq0, k0, k1);
            float s1 = dot8(aq1, k0, k1);
            float p0 = __expf(s0 * SCALEF);
            float p1 = __expf(s1 * SCALEF);
            l0 += p0; l1 += p1;
            float4 v0 = *(const float4*)&v_sw[m*20 + hk0];
            float4 v1 = *(const float4*)&v_sw[m*20 + hk0 + 4];
            acc8(o0, p0, v0, v1); acc8(o1, p1, v0, v1);
        }
        float i0 = 1.f / l0, i1 = 1.f / l1;
        #pragma unroll
        for (int j = 0; j < 8; j++) {
            o_sw[n0*17 + hk0 + j] = o0[j] * i0;
            o_sw[n1*17 + hk0 + j] = o1[j] * i1;
        }
    }
    __syncthreads();

    // projection: 2 tokens x 48 channels; write into xs
    {
        float orr0[16], orr1[16];
        #pragma unroll
        for (int j = 0; j < 16; j++) { orr0[j] = o_sw[n0*17 + j]; orr1[j] = o_sw[n1*17 + j]; }
        const int c0 = half * 48;
        for (int cc = 0; cc < 48; cc++) {
            int c = c0 + cc;
            const float4* wp = (const float4*)&WoT_s[c*16];
            float4 w0 = wp[0], w1 = wp[1], w2 = wp[2], w3 = wp[3];
            float y0 = bo_s[c], y1 = bo_s[c];
            y0 += orr0[0]*w0.x + orr0[1]*w0.y + orr0[2]*w0.z + orr0[3]*w0.w
                + orr0[4]*w1.x + orr0[5]*w1.y + orr0[6]*w1.z + orr0[7]*w1.w
                + orr0[8]*w2.x + orr0[9]*w2.y + orr0[10]*w2.z + orr0[11]*w2.w
                + orr0[12]*w3.x + orr0[13]*w3.y + orr0[14]*w3.z + orr0[15]*w3.w;
            y1 += orr1[0]*w0.x + orr1[1]*w0.y + orr1[2]*w0.z + orr1[3]*w0.w
                + orr1[4]*w1.x + orr1[5]*w1.y + orr1[6]*w1.z + orr1[7]*w1.w
                + orr1[8]*w2.x + orr1[9]*w2.y + orr1[10]*w2.z + orr1[11]*w2.w
                + orr1[12]*w3.x + orr1[13]*w3.y + orr1[14]*w3.z + orr1[15]*w3.w;
            xsw[n0*97 + c] = y0;
            xsw[n1*97 + c] = y1;
        }
    }
    __syncthreads();

    // scatter back
    for (int idx = tid; idx < 3072; idx += 128) {
        int wv2, rem;
        if (idx >= 1536) { wv2 = 1; rem = idx - 1536; } else { wv2 = 0; rem = idx; }
        int r = rem / 24, c4 = (rem - r * 24) * 4;
        int wid = wid0 + wv2;
        int wh = wid / NWW, ww = wid % NWW;
        int i = r >> 3, j = r & 7;
        int h = (wh * 8 + i + 4) & (H_ - 1);
        int w = ww * 8 + j + 4; if (w >= W_) w -= W_;
        const float* row = xs + wv2 * 6208 + r * 97 + c4;
        *(float4*)&g_buf1[btoff + (h * W_ + w) * C_ + c4] =
            make_float4(row[0], row[1], row[2], row[3]);
    }
}

// =====================================================================
// Kernel 2: temporal MSA, 16 w-locations/block (2 groups of 8)
// 3072 blocks, 128 threads. smem 100928 B.
// =====================================================================
__global__ __launch_bounds__(128) void k_temporal(
    const float* __restrict__ Wq, const float* __restrict__ bq,
    const float* __restrict__ Wk, const float* __restrict__ bk,
    const float* __restrict__ Wv, const float* __restrict__ bv,
    const float* __restrict__ Wo, const float* __restrict__ bo)
{
    extern __shared__ float sm[];
    float* Wq_s  = sm;
    float* Wk_s  = sm + 1536;
    float* Wv_s  = sm + 3072;
    float* WoT_s = sm + 4608;
    float* bq_s  = sm + 6144;
    float* bk_s  = sm + 6160;
    float* bv_s  = sm + 6176;
    float* bo_s  = sm + 6192;
    float* xs    = sm + 6288;    // 2 x (64 x 97); row = l*8+t
    float* k_sb  = sm + 18704;   // 2 x (8 x 136)
    float* v_sb  = sm + 20880;   // 2 x (8 x 136)
    float* o_sb  = sm + 23056;   // 2 x (64 x 17)

    const int tid  = threadIdx.x;
    const int g    = tid >> 6;          // location group (8 locations)
    const int half = (tid >> 5) & 1;
    const int p    = tid & 31;
    const int hk0  = half * 8;

    for (int i = tid; i < 1536; i += 128) {
        Wq_s[i] = Wq[i]; Wk_s[i] = Wk[i]; Wv_s[i] = Wv[i];
        WoT_s[i] = Wo[(i & 15) * 96 + (i >> 4)];
    }
    for (int i = tid; i < 96; i += 128) bo_s[i] = bo[i];
    if (tid < 16) { bq_s[tid] = bq[tid]; bk_s[tid] = bk[tid]; bv_s[tid] = bv[tid]; }

    const int b   = blockIdx.x / (H_ * 12);
    const int rem = blockIdx.x % (H_ * 12);
    const int h   = rem / 12;
    const int w0  = (rem % 12) * 16;

    for (int idx = tid; idx < 3072; idx += 128) {
        int g2, rm;
        if (idx >= 1536) { g2 = 1; rm = idx - 1536; } else { g2 = 0; rm = idx; }
        int r = rm / 24, c4 = (rm - r * 24) * 4;
        int rl = r >> 3, rt = r & 7;
        float4 vv = *(const float4*)&g_buf1[((b*8 + rt)*H_ + h)*(W_*C_) + (w0 + g2*8 + rl)*C_ + c4];
        float* row = xs + g2 * 6208 + r * 97 + c4;
        row[0] = vv.x; row[1] = vv.y; row[2] = vv.z; row[3] = vv.w;
    }
    __syncthreads();

    float* xsg  = xs   + g * 6208;
    float* k_sg = k_sb + g * 1088;
    float* v_sg = v_sb + g * 1088;
    float* o_sg = o_sb + g * 1088;
    const int n0 = p, n1 = p + 32;
    const int l0i = n0 >> 3, t0i = n0 & 7;
    const int l1i = n1 >> 3, t1i = n1 & 7;

    float aq0[8], aq1[8];
    {
        float ak0[8], ak1[8], av0[8], av1[8];
        #pragma unroll
        for (int j = 0; j < 8; j++) {
            aq0[j] = bq_s[hk0+j]; aq1[j] = bq_s[hk0+j];
            ak0[j] = bk_s[hk0+j]; ak1[j] = bk_s[hk0+j];
            av0[j] = bv_s[hk0+j]; av1[j] = bv_s[hk0+j];
        }
        for (int c = 0; c < 96; c++) {
            float x0 = xsg[n0 * 97 + c];
            float x1 = xsg[n1 * 97 + c];
            float4 wq0 = *(const float4*)&Wq_s[c*16 + hk0];
            float4 wq1 = *(const float4*)&Wq_s[c*16 + hk0 + 4];
            acc8(aq0, x0, wq0, wq1); acc8(aq1, x1, wq0, wq1);
            float4 wk0 = *(const float4*)&Wk_s[c*16 + hk0];
            float4 wk1 = *(const float4*)&Wk_s[c*16 + hk0 + 4];
            acc8(ak0, x0, wk0, wk1); acc8(ak1, x1, wk0, wk1);
            float4 wv0 = *(const float4*)&Wv_s[c*16 + hk0];
            float4 wv1 = *(const float4*)&Wv_s[c*16 + hk0 + 4];
            acc8(av0, x0, wv0, wv1); acc8(av1, x1, wv0, wv1);
        }
        *(float4*)&k_sg[l0i*136 + t0i*16 + hk0]     = make_float4(ak0[0],ak0[1],ak0[2],ak0[3]);
        *(float4*)&k_sg[l0i*136 + t0i*16 + hk0 + 4] = make_float4(ak0[4],ak0[5],ak0[6],ak0[7]);
        *(float4*)&k_sg[l1i*136 + t1i*16 + hk0]     = make_float4(ak1[0],ak1[1],ak1[2],ak1[3]);
        *(float4*)&k_sg[l1i*136 + t1i*16 + hk0 + 4] = make_float4(ak1[4],ak1[5],ak1[6],ak1[7]);
        *(float4*)&v_sg[l0i*136 + t0i*16 + hk0]     = make_float4(av0[0],av0[1],av0[2],av0[3]);
        *(float4*)&v_sg[l0i*136 + t0i*16 + hk0 + 4] = make_float4(av0[4],av0[5],av0[6],av0[7]);
        *(float4*)&v_sg[l1i*136 + t1i*16 + hk0]     = make_float4(av1[0],av1[1],av1[2],av1[3]);
        *(float4*)&v_sg[l1i*136 + t1i*16 + hk0 + 4] = make_float4(av1[4],av1[5],av1[6],av1[7]);
    }
    __syncthreads();

    // temporal attention over T=8 for the two tokens (different locations)
    {
        float o0[8] = {0,0,0,0,0,0,0,0}, o1[8] = {0,0,0,0,0,0,0,0};
        float l0 = 0.f, l1 = 0.f;
        #pragma unroll
        for (int m = 0; m < 8; m++) {
            float4 ka0 = *(const float4*)&k_sg[l0i*136 + m*16 + hk0];
            float4 ka1 = *(const float4*)&k_sg[l0i*136 + m*16 + hk0 + 4];
            float4 kb0 = *(const float4*)&k_sg[l1i*136 + m*16 + hk0];
            float4 kb1 = *(const float4*)&k_sg[l1i*136 + m*16 + hk0 + 4];
            float s0 = dot8(aq0, ka0, ka1);
            float s1 = dot8(aq1, kb0, kb1);
            float p0 = __expf(s0 * SCALEF);
            float p1 = __expf(s1 * SCALEF);
            l0 += p0; l1 += p1;
            float4 va0 = *(const float4*)&v_sg[l0i*136 + m*16 + hk0];
            float4 va1 = *(const float4*)&v_sg[l0i*136 + m*16 + hk0 + 4];
            float4 vb0 = *(const float4*)&v_sg[l1i*136 + m*16 + hk0];
            float4 vb1 = *(const float4*)&v_sg[l1i*136 + m*16 + hk0 + 4];
            acc8(o0, p0, va0, va1); acc8(o1, p1, vb0, vb1);
        }
        float i0 = 1.f / l0, i1 = 1.f / l1;
        #pragma unroll
        for (int j = 0; j < 8; j++) {
            o_sg[n0*17 + hk0 + j] = o0[j] * i0;
            o_sg[n1*17 + hk0 + j] = o1[j] * i1;
        }
    }
    __syncthreads();

    {
        float orr0[16], orr1[16];
        #pragma unroll
        for (int j = 0; j < 16; j++) { orr0[j] = o_sg[n0*17 + j]; orr1[j] = o_sg[n1*17 + j]; }
        const int c0 = half * 48;
        for (int cc = 0; cc < 48; cc++) {
            int c = c0 + cc;
            const float4* wp = (const float4*)&WoT_s[c*16];
            float4 w0 = wp[0], w1 = wp[1], w2 = wp[2], w3 = wp[3];
            float y0 = bo_s[c], y1 = bo_s[c];
            y0 += orr0[0]*w0.x + orr0[1]*w0.y + orr0[2]*w0.z + orr0[3]*w0.w
                + orr0[4]*w1.x + orr0[5]*w1.y + orr0[6]*w1.z + orr0[7]*w1.w
                + orr0[8]*w2.x + orr0[9]*w2.y + orr0[10]*w2.z + orr0[11]*w2.w
                + orr0[12]*w3.x + orr0[13]*w3.y + orr0[14]*w3.z + orr0[15]*w3.w;
            y1 += orr1[0]*w0.x + orr1[1]*w0.y + orr1[2]*w0.z + orr1[3]*w0.w
                + orr1[4]*w1.x + orr1[5]*w1.y + orr1[6]*w1.z + orr1[7]*w1.w
                + orr1[8]*w2.x + orr1[9]*w2.y + orr1[10]*w2.z + orr1[11]*w2.w
                + orr1[12]*w3.x + orr1[13]*w3.y + orr1[14]*w3.z + orr1[15]*w3.w;
            xsg[n0*97 + c] = y0;
            xsg[n1*97 + c] = y1;
        }
    }
    __syncthreads();

    for (int idx = tid; idx < 3072; idx += 128) {
        int g2, rm;
        if (idx >= 1536) { g2 = 1; rm = idx - 1536; } else { g2 = 0; rm = idx; }
        int r = rm / 24, c4 = (rm - r * 24) * 4;
        int rl = r >> 3, rt = r & 7;
        const float* row = xs + g2 * 6208 + r * 97 + c4;
        *(float4*)&g_buf2[((b*8 + rt)*H_ + h)*(W_*C_) + (w0 + g2*8 + rl)*C_ + c4] =
            make_float4(row[0], row[1], row[2], row[3]);
    }
}

// =====================================================================
// Kernel 3: LN2 + MLP via 3xTF32 mma.sync  (592 blocks, 256 thr)
// warp w: rows (w>>1)*16, cols (w&1)*48; 6 n-tiles x 12 k-steps
// =====================================================================
__global__ __launch_bounds__(256) void k_mlp(
    const float* __restrict__ g2, const float* __restrict__ b2,
    const float* __restrict__ W1, const float* __restrict__ b1m,
    const float* __restrict__ W2, const float* __restrict__ b2m,
    float* __restrict__ out)
{
    extern __shared__ float sm[];
    float* W1_s = sm;                 // 96 x 97
    float* W2_s = sm + 9312;          // 96 x 97
    float* g_s  = sm + 18624;
    float* bb_s = sm + 18720;
    float* b1_s = sm + 18816;
    float* b2_s = sm + 18912;
    float* xn   = sm + 19008;         // 64 x 97

    const int tid  = threadIdx.x;
    const int lane = tid & 31;
    const int warp = tid >> 5;
    const int row0 = (warp >> 1) * 16;
    const int col0 = (warp & 1) * 48;
    const int r    = lane >> 2;       // 0..7
    const int cA   = lane & 3;        // 0..3

    // scalar stores: stride 97 is odd, float4 would be misaligned
    for (int i = tid; i < 9216; i += 256) {
        int rr = i / 96, cc = i - rr * 96;
        W1_s[rr*97 + cc] = W1[i];
        W2_s[rr*97 + cc] = W2[i];
    }
    if (tid < 96) { g_s[tid] = g2[tid]; bb_s[tid] = b2[tid]; b1_s[tid] = b1m[tid]; b2_s[tid] = b2m[tid]; }
    __syncthreads();

    for (int tile = blockIdx.x; tile < NTOTAL / 64; tile += gridDim.x) {
        const float* src = g_buf2 + tile * 6144;
        for (int idx = tid; idx < 1536; idx += 256) {
            int t = idx / 24, c4 = (idx - t * 24) * 4;
            float4 vv = *(const float4*)&src[t * 96 + c4];
            float* row = xn + t * 97 + c4;
            row[0] = vv.x; row[1] = vv.y; row[2] = vv.z; row[3] = vv.w;
        }
        __syncthreads();

        // LN (8 warps x 8 tokens)
        for (int t = warp * 8; t < warp * 8 + 8; t++) {
            float* row = xn + t * 97;
            float a0 = row[lane], a1 = row[lane + 32], a2 = row[lane + 64];
            float s  = a0 + a1 + a2;
            float s2 = a0*a0 + a1*a1 + a2*a2;
            #pragma unroll
            for (int off = 16; off > 0; off >>= 1) {
                s  += __shfl_xor_sync(0xffffffff, s,  off);
                s2 += __shfl_xor_sync(0xffffffff, s2, off);
            }
            float mu = s * (1.f/96.f);
            float var = s2 * (1.f/96.f) - mu * mu;
            float rs = rsqrtf(var + EPSF);
            row[lane]      = (a0 - mu) * rs * g_s[lane]      + bb_s[lane];
            row[lane + 32] = (a1 - mu) * rs * g_s[lane + 32] + bb_s[lane + 32];
            row[lane + 64] = (a2 - mu) * rs * g_s[lane + 64] + bb_s[lane + 64];
        }
        __syncthreads();

        // ---- layer 1: hidden = relu(xn @ W1 + b1) via 3xTF32 mma ----
        float acc[6][4];
        {
            const int bcolbase = col0 + cA * 2;
            #pragma unroll
            for (int n = 0; n < 6; n++) {
                float bv0 = b1_s[bcolbase + n*8], bv1 = b1_s[bcolbase + n*8 + 1];
                acc[n][0] = bv0; acc[n][1] = bv1; acc[n][2] = bv0; acc[n][3] = bv1;
            }
            for (int k = 0; k < 12; k++) {
                unsigned ah[4], al[4];
                split_tf32(xn[(row0+r)*97   + k*8 + cA],     ah[0], al[0]);
                split_tf32(xn[(row0+r+8)*97 + k*8 + cA],     ah[1], al[1]);
                split_tf32(xn[(row0+r)*97   + k*8 + cA + 4], ah[2], al[2]);
                split_tf32(xn[(row0+r+8)*97 + k*8 + cA + 4], ah[3], al[3]);
                #pragma unroll
                for (int n = 0; n < 6; n++) {
                    int bc = col0 + n*8 + r;
                    unsigned bh0, bl0, bh1, bl1;
                    split_tf32(W1_s[(k*8 + cA)*97     + bc], bh0, bl0);
                    split_tf32(W1_s[(k*8 + cA + 4)*97 + bc], bh1, bl1);
                    mma8(acc[n], ah, bh0, bh1);
                    mma8(acc[n], ah, bl0, bl1);
                    mma8(acc[n], al, bh0, bh1);
                }
            }
        }
        __syncthreads();
        #pragma unroll
        for (int n = 0; n < 6; n++) {
            int bcol = col0 + n*8 + cA*2;
            xn[(row0+r)*97   + bcol]     = fmaxf(acc[n][0], 0.f);
            xn[(row0+r)*97   + bcol + 1] = fmaxf(acc[n][1], 0.f);
            xn[(row0+r+8)*97 + bcol]     = fmaxf(acc[n][2], 0.f);
            xn[(row0+r+8)*97 + bcol + 1] = fmaxf(acc[n][3], 0.f);
        }
        __syncthreads();

        // ---- layer 2: out = relu(hidden @ W2 + b2) ----
        {
            const int bcolbase = col0 + cA * 2;
            #pragma unroll
            for (int n = 0; n < 6; n++) {
                float bv0 = b2_s[bcolbase + n*8], bv1 = b2_s[bcolbase + n*8 + 1];
                acc[n][0] = bv0; acc[n][1] = bv1; acc[n][2] = bv0; acc[n][3] = bv1;
            }
            for (int k = 0; k < 12; k++) {
                unsigned ah[4], al[4];
                split_tf32(xn[(row0+r)*97   + k*8 + cA],     ah[0], al[0]);
                split_tf32(xn[(row0+r+8)*97 + k*8 + cA],     ah[1], al[1]);
                split_tf32(xn[(row0+r)*97   + k*8 + cA + 4], ah[2], al[2]);
                split_tf32(xn[(row0+r+8)*97 + k*8 + cA + 4], ah[3], al[3]);
                #pragma unroll
                for (int n = 0; n < 6; n++) {
                    int bc = col0 + n*8 + r;
                    unsigned bh0, bl0, bh1, bl1;
                    split_tf32(W2_s[(k*8 + cA)*97     + bc], bh0, bl0);
                    split_tf32(W2_s[(k*8 + cA + 4)*97 + bc], bh1, bl1);
                    mma8(acc[n], ah, bh0, bh1);
                    mma8(acc[n], ah, bl0, bl1);
                    mma8(acc[n], al, bh0, bh1);
                }
            }
        }
        float* dst = out + tile * 6144;
        #pragma unroll
        for (int n = 0; n < 6; n++) {
            int bcol = col0 + n*8 + cA*2;
            dst[(row0+r)*96   + bcol]     = fmaxf(acc[n][0], 0.f);
            dst[(row0+r)*96   + bcol + 1] = fmaxf(acc[n][1], 0.f);
            dst[(row0+r+8)*96 + bcol]     = fmaxf(acc[n][2], 0.f);
            dst[(row0+r+8)*96 + bcol + 1] = fmaxf(acc[n][3], 0.f);
        }
        __syncthreads();
    }
}

// =====================================================================
extern "C" void kernel_launch(void* const* d_in, const int* in_sizes, int n_in,
                              void* d_out, int out_size)
{
    const float* x   = (const float*)d_in[0];
    const float* g1  = (const float*)d_in[1];
    const float* b1  = (const float*)d_in[2];
    const float* g2  = (const float*)d_in[3];
    const float* b2  = (const float*)d_in[4];
    const float* Wq  = (const float*)d_in[5];
    const float* bq  = (const float*)d_in[6];
    const float* Wk  = (const float*)d_in[7];
    const float* bk  = (const float*)d_in[8];
    const float* Wv  = (const float*)d_in[9];
    const float* bv  = (const float*)d_in[10];
    const float* Wo  = (const float*)d_in[11];
    const float* bo  = (const float*)d_in[12];
    const float* W1  = (const float*)d_in[13];
    const float* b1m = (const float*)d_in[14];
    const float* W2  = (const float*)d_in[15];
    const float* b2m = (const float*)d_in[16];
    float* out = (float*)d_out;

    cudaFuncSetAttribute(k_spatial,  cudaFuncAttributeMaxDynamicSharedMemorySize, 104768);
    cudaFuncSetAttribute(k_temporal, cudaFuncAttributeMaxDynamicSharedMemorySize, 100928);
    cudaFuncSetAttribute(k_mlp,      cudaFuncAttributeMaxDynamicSharedMemorySize, 100864);

    k_spatial<<<3072, 128, 104768>>>(x, g1, b1, Wq, bq, Wk, bk, Wv, bv, Wo, bo);
    k_temporal<<<3072, 128, 100928>>>(Wq, bq, Wk, bk, Wv, bv, Wo, bo);
    k_mlp<<<592, 256, 100864>>>(g2, b2, W1, b1m, W2, b2m, out);
}